// round 4
// baseline (speedup 1.0000x reference)
#include <cuda_runtime.h>
#include <math.h>

#define B_      256
#define NIN_    6912
#define NCH     8          // n per stage
#define NITER   2          // stages per block
#define SLOTS   8
#define THREADS 128

typedef unsigned long long ull;

#define FFMA2(d, a, b, c) \
    asm("fma.rn.f32x2 %0, %1, %2, %3;" : "=l"(d) : "l"(a), "l"(b), "l"(c))
#define FMUL2(d, a, b) \
    asm("mul.rn.f32x2 %0, %1, %2;" : "=l"(d) : "l"(a), "l"(b))
#define PACK2(d, lo, hi) \
    asm("mov.b64 %0, {%1, %2};" : "=l"(d) : "f"(lo), "f"(hi))
#define UNPACK2(lo, hi, v) \
    asm("mov.b64 {%0, %1}, %2;" : "=f"(lo), "=f"(hi) : "l"(v))

// Scratch, transposed [slot][k][b] (k = j*16+e) so warp atomics coalesce.
__device__ float g_s1[SLOTS * B_ * 32];
__device__ float g_s2[SLOTS * B_ * 32];
__device__ float g_v1[B_ * 32];

__global__ void zero_kernel() {
    int i = blockIdx.x * blockDim.x + threadIdx.x;
    if (i < SLOTS * B_ * 32) { g_s1[i] = 0.0f; g_s2[i] = 0.0f; }
}

__device__ __forceinline__ void squash16(const float* s, float* v) {
    float n2 = 0.0f;
#pragma unroll
    for (int e = 0; e < 16; ++e) n2 = fmaf(s[e], s[e], n2);
    float f = n2 / ((1.0f + n2) * sqrtf(n2 + 1e-9f));
#pragma unroll
    for (int e = 0; e < 16; ++e) v[e] = s[e] * f;
}

// W chunk -> smem: Ws[nl][j*32 + 2e + h], 512 float4.
__device__ __forceinline__ void stage_W(float4 (*Ws)[64], const float4* __restrict__ W,
                                        int n0, int tid) {
#pragma unroll
    for (int it = 0; it < 4; ++it) {
        int f  = it * THREADS + tid;        // 0..511
        int j  = f >> 8;
        int nl = (f >> 5) & 7;
        int kk = f & 31;
        Ws[nl][j * 32 + kk] = W[((size_t)(j * NIN_ + n0 + nl)) * 32 + kk];
    }
}

// x chunk -> smem transposed + d-pair packed: xs[nl][dp][bl]
template <int BGRP>
__device__ __forceinline__ void stage_x(ull (*xs)[4][BGRP + 1], const float4* __restrict__ X,
                                        int bbase, int n0, int tid) {
#pragma unroll
    for (int it = 0; it < (BGRP * NCH * 2) / THREADS; ++it) {
        int f  = it * THREADS + tid;
        int bl = f >> 4;                    // 16 float4 per b per chunk
        int q  = f & 15;
        int nl = q >> 1;
        int dh = q & 1;
        float4 v = X[((size_t)(bbase + bl) * NIN_ + n0 + nl) * 2 + dh];
        ull p0, p1;
        PACK2(p0, v.x, v.y);
        PACK2(p1, v.z, v.w);
        xs[nl][dh * 2][bl]     = p0;
        xs[nl][dh * 2 + 1][bl] = p1;
    }
}

// ---------------- Pass 1: j-split, 2 b per thread ----------------
#define BGRP1 128
__global__ __launch_bounds__(THREADS, 4) void pass1_kernel(const float4* __restrict__ X,
                                                           const float4* __restrict__ W) {
    __shared__ float4 Ws[NCH][64];
    __shared__ ull xs[NCH][4][BGRP1 + 1];
    const int tid   = threadIdx.x;
    const int j     = tid & 1;
    const int bl    = (tid >> 1) << 1;          // this thread: local b = bl, bl+1
    const int bbase = blockIdx.y * BGRP1;

    ull acc[2][16];
    ull zero; PACK2(zero, 0.0f, 0.0f);
#pragma unroll
    for (int p = 0; p < 2; ++p)
#pragma unroll
        for (int e = 0; e < 16; ++e) acc[p][e] = zero;

#pragma unroll 1
    for (int it = 0; it < NITER; ++it) {
        const int n0 = (blockIdx.x * NITER + it) * NCH;
        if (it) __syncthreads();
        stage_W(Ws, W, n0, tid);
        stage_x<BGRP1>(xs, X, bbase, n0, tid);
        __syncthreads();

#pragma unroll
        for (int n = 0; n < NCH; ++n) {
            ull xa0 = xs[n][0][bl],     xa1 = xs[n][1][bl];
            ull xa2 = xs[n][2][bl],     xa3 = xs[n][3][bl];
            ull xb0 = xs[n][0][bl + 1], xb1 = xs[n][1][bl + 1];
            ull xb2 = xs[n][2][bl + 1], xb3 = xs[n][3][bl + 1];
#pragma unroll
            for (int e = 0; e < 16; ++e) {
                const ulonglong2 wA = *reinterpret_cast<const ulonglong2*>(&Ws[n][j * 32 + 2 * e]);
                const ulonglong2 wB = *reinterpret_cast<const ulonglong2*>(&Ws[n][j * 32 + 2 * e + 1]);
                ull a = acc[0][e];
                FFMA2(a, wA.x, xa0, a); FFMA2(a, wA.y, xa1, a);
                FFMA2(a, wB.x, xa2, a); FFMA2(a, wB.y, xa3, a);
                acc[0][e] = a;
                ull b = acc[1][e];
                FFMA2(b, wA.x, xb0, b); FFMA2(b, wA.y, xb1, b);
                FFMA2(b, wB.x, xb2, b); FFMA2(b, wB.y, xb3, b);
                acc[1][e] = b;
            }
        }
    }

    float* dst = g_s1 + ((blockIdx.x + blockIdx.y) & (SLOTS - 1)) * (B_ * 32);
#pragma unroll
    for (int e = 0; e < 16; ++e) {
        float lo, hi;
        UNPACK2(lo, hi, acc[0][e]);
        atomicAdd(dst + (j * 16 + e) * B_ + bbase + bl, lo + hi);
        UNPACK2(lo, hi, acc[1][e]);
        atomicAdd(dst + (j * 16 + e) * B_ + bbase + bl + 1, lo + hi);
    }
}

// ---------------- v1 = squash(0.5 * sum_slots s1) ----------------
__global__ void v1_kernel() {
    const int b = threadIdx.x;
    float s[32];
#pragma unroll
    for (int k = 0; k < 32; ++k) s[k] = 0.0f;
#pragma unroll
    for (int sl = 0; sl < SLOTS; ++sl)
#pragma unroll
        for (int k = 0; k < 32; ++k)
            s[k] += g_s1[sl * (B_ * 32) + k * B_ + b];
#pragma unroll
    for (int k = 0; k < 32; ++k) s[k] *= 0.5f;
    float v[32];
    squash16(s, v);
    squash16(s + 16, v + 16);
#pragma unroll
    for (int k = 0; k < 32; ++k) g_v1[k * B_ + b] = v[k];
}

// ---------------- Pass 2: j-split, packed routing, shfl logit exchange ----------------
#define BGRP2 64
__global__ __launch_bounds__(THREADS, 4) void pass2_kernel(const float4* __restrict__ X,
                                                           const float4* __restrict__ W) {
    __shared__ float4 Ws[NCH][64];
    __shared__ ull xs[NCH][4][BGRP2 + 1];
    const int tid   = threadIdx.x;
    const int j     = tid & 1;
    const int bl    = tid >> 1;                 // 0..63
    const int bbase = blockIdx.y * BGRP2;
    const int b     = bbase + bl;

    // v1 for my (b, j), duplicated into both f32x2 halves
    ull v1d[16];
#pragma unroll
    for (int e = 0; e < 16; ++e) {
        float v = g_v1[(j * 16 + e) * B_ + b];
        PACK2(v1d[e], v, v);
    }

    ull acc[16];
    ull zero; PACK2(zero, 0.0f, 0.0f);
#pragma unroll
    for (int e = 0; e < 16; ++e) acc[e] = zero;

#pragma unroll 1
    for (int it = 0; it < NITER; ++it) {
        const int n0 = (blockIdx.x * NITER + it) * NCH;
        if (it) __syncthreads();
        stage_W(Ws, W, n0, tid);
        stage_x<BGRP2>(xs, X, bbase, n0, tid);
        __syncthreads();

#pragma unroll
        for (int n = 0; n < NCH; ++n) {
            ull x0 = xs[n][0][bl], x1 = xs[n][1][bl];
            ull x2 = xs[n][2][bl], x3 = xs[n][3][bl];

            ull u2[16];
            ull t2 = zero;
#pragma unroll
            for (int e = 0; e < 16; ++e) {
                const ulonglong2 wA = *reinterpret_cast<const ulonglong2*>(&Ws[n][j * 32 + 2 * e]);
                const ulonglong2 wB = *reinterpret_cast<const ulonglong2*>(&Ws[n][j * 32 + 2 * e + 1]);
                ull t;
                FMUL2(t, wA.x, x0);
                FFMA2(t, wA.y, x1, t);
                FFMA2(t, wB.x, x2, t);
                FFMA2(t, wB.y, x3, t);
                u2[e] = t;
                FFMA2(t2, v1d[e], t, t2);      // packed logit partial
            }
            float tlo, thi;
            UNPACK2(tlo, thi, t2);
            float tj = tlo + thi;                       // my capsule's logit
            float to = __shfl_xor_sync(0xffffffffu, tj, 1);  // partner capsule's logit
            float c  = __fdividef(1.0f, 1.0f + __expf(to - tj));
            ull cd; PACK2(cd, c, c);
#pragma unroll
            for (int e = 0; e < 16; ++e)
                FFMA2(acc[e], cd, u2[e], acc[e]);
        }
    }

    float* dst = g_s2 + ((blockIdx.x + blockIdx.y) & (SLOTS - 1)) * (B_ * 32);
#pragma unroll
    for (int e = 0; e < 16; ++e) {
        float lo, hi;
        UNPACK2(lo, hi, acc[e]);
        atomicAdd(dst + (j * 16 + e) * B_ + b, lo + hi);
    }
}

// ---------------- Output ----------------
__global__ void squash_out_kernel(float* __restrict__ out) {
    int t = blockIdx.x * blockDim.x + threadIdx.x;   // t = b*2 + j
    if (t < B_ * 2) {
        int b = t >> 1, j = t & 1;
        float s[16];
#pragma unroll
        for (int e = 0; e < 16; ++e) s[e] = 0.0f;
#pragma unroll
        for (int sl = 0; sl < SLOTS; ++sl)
#pragma unroll
            for (int e = 0; e < 16; ++e)
                s[e] += g_s2[sl * (B_ * 32) + (j * 16 + e) * B_ + b];
        float v[16];
        squash16(s, v);
#pragma unroll
        for (int e = 0; e < 16; ++e) out[t * 16 + e] = v[e];
    }
}

extern "C" void kernel_launch(void* const* d_in, const int* in_sizes, int n_in,
                              void* d_out, int out_size) {
    const float4* X = (const float4*)d_in[0];   // x: [256, 6912, 8] f32
    const float4* W = (const float4*)d_in[1];   // W: [2, 6912, 16, 8] f32
    float* out = (float*)d_out;                 // v: [256, 2, 16] f32

    zero_kernel<<<(SLOTS * B_ * 32 + 255) / 256, 256>>>();

    dim3 g1(NIN_ / (NCH * NITER), B_ / BGRP1);  // 432 x 2
    pass1_kernel<<<g1, THREADS>>>(X, W);

    v1_kernel<<<1, B_>>>();

    dim3 g2(NIN_ / (NCH * NITER), B_ / BGRP2);  // 432 x 4
    pass2_kernel<<<g2, THREADS>>>(X, W);

    squash_out_kernel<<<2, 256>>>(out);
}

// round 5
// speedup vs baseline: 1.3869x; 1.3869x over previous
#include <cuda_runtime.h>
#include <math.h>
#include <stdint.h>

#define B_      256
#define NIN_    6912
#define SLOTS   8

typedef unsigned long long ull;

#define FFMA2(d, a, b, c) \
    asm("fma.rn.f32x2 %0, %1, %2, %3;" : "=l"(d) : "l"(a), "l"(b), "l"(c))
#define FMUL2(d, a, b) \
    asm("mul.rn.f32x2 %0, %1, %2;" : "=l"(d) : "l"(a), "l"(b))
#define PACK2(d, lo, hi) \
    asm("mov.b64 %0, {%1, %2};" : "=l"(d) : "f"(lo), "f"(hi))
#define UNPACK2(lo, hi, v) \
    asm("mov.b64 {%0, %1}, %2;" : "=f"(lo), "=f"(hi) : "l"(v))

__device__ __forceinline__ uint32_t s2u(const void* p) {
    return (uint32_t)__cvta_generic_to_shared(p);
}
__device__ __forceinline__ void cp16(const void* sdst, const void* gsrc) {
    asm volatile("cp.async.cg.shared.global [%0], [%1], 16;"
                 :: "r"(s2u(sdst)), "l"(gsrc) : "memory");
}
#define CP_COMMIT() asm volatile("cp.async.commit_group;" ::: "memory")
template <int N>
__device__ __forceinline__ void cp_wait() {
    asm volatile("cp.async.wait_group %0;" :: "n"(N) : "memory");
}

// Scratch. s1/s2 transposed [slot][k][b] (k=j*16+e) for coalesced atomics.
// v1 stored [b][k] for vectorized per-thread reads in pass2.
__device__ float g_s1[SLOTS * B_ * 32];
__device__ float g_s2[SLOTS * B_ * 32];
__device__ __align__(16) float g_v1[B_ * 32];

__global__ void zero_kernel() {
    int i = blockIdx.x * blockDim.x + threadIdx.x;
    if (i < SLOTS * B_ * 32) { g_s1[i] = 0.0f; g_s2[i] = 0.0f; }
}

__device__ __forceinline__ void squash16(const float* s, float* v) {
    float n2 = 0.0f;
#pragma unroll
    for (int e = 0; e < 16; ++e) n2 = fmaf(s[e], s[e], n2);
    float f = n2 / ((1.0f + n2) * sqrtf(n2 + 1e-9f));
#pragma unroll
    for (int e = 0; e < 16; ++e) v[e] = s[e] * f;
}

// ======================= Pass 1 =======================
// 128 threads: j = tid&1, bp = tid>>1 -> handles b = {2bp, 2bp+1} for capsule j.
// 16 n per block (4 stages x 4 n), double-buffered cp.async pipeline.
#define P1_NCH 4
#define P1_STG 4
#define P1_THR 128
#define P1_BG  128

__global__ __launch_bounds__(P1_THR, 4) void pass1_kernel(const float4* __restrict__ X,
                                                          const float4* __restrict__ Wg) {
    __shared__ float4 Wd[2][P1_NCH][16][2][2];        // [buf][nl][e][h][j]
    __shared__ float4 xs[2][P1_BG][P1_NCH * 2 + 1];   // row pad 16B

    const int tid   = threadIdx.x;
    const int j     = tid & 1;
    const int bp    = tid >> 1;              // 0..63
    const int lb0   = bp * 2, lb1 = bp * 2 + 1;
    const int gbb   = blockIdx.y * P1_BG;
    const int nbase = blockIdx.x * (P1_NCH * P1_STG);

    ull acc0[16], acc1[16];
    ull zero; PACK2(zero, 0.0f, 0.0f);
#pragma unroll
    for (int e = 0; e < 16; ++e) { acc0[e] = zero; acc1[e] = zero; }

    auto issue = [&](int s) {
        const int buf = s & 1;
        const int n0  = nbase + s * P1_NCH;
        // W: 256 float4 per stage, 2 per thread
#pragma unroll
        for (int w = 0; w < 2; ++w) {
            int f  = w * P1_THR + tid;
            int jj = f & 1, h = (f >> 1) & 1, e = (f >> 2) & 15, nl = (f >> 6) & 3;
            cp16(&Wd[buf][nl][e][h][jj],
                 Wg + ((size_t)(jj * NIN_ + n0 + nl) * 16 + e) * 2 + h);
        }
        // x: 128b * 8 float4 = 1024, 8 per thread
#pragma unroll
        for (int it = 0; it < 8; ++it) {
            int f = it * P1_THR + tid;
            int bl = f >> 3, q = f & 7, nl = q >> 1, h = q & 1;
            cp16(&xs[buf][bl][nl * 2 + h],
                 X + ((size_t)(gbb + bl) * NIN_ + n0 + nl) * 2 + h);
        }
        CP_COMMIT();
    };

    auto compute = [&](int s) {
        const int buf = s & 1;
#pragma unroll
        for (int nl = 0; nl < P1_NCH; ++nl) {
            ulonglong2 xa0 = *reinterpret_cast<const ulonglong2*>(&xs[buf][lb0][nl * 2]);
            ulonglong2 xa1 = *reinterpret_cast<const ulonglong2*>(&xs[buf][lb0][nl * 2 + 1]);
            ulonglong2 xb0 = *reinterpret_cast<const ulonglong2*>(&xs[buf][lb1][nl * 2]);
            ulonglong2 xb1 = *reinterpret_cast<const ulonglong2*>(&xs[buf][lb1][nl * 2 + 1]);
#pragma unroll
            for (int e = 0; e < 16; ++e) {
                ulonglong2 wA = *reinterpret_cast<const ulonglong2*>(&Wd[buf][nl][e][0][j]);
                ulonglong2 wB = *reinterpret_cast<const ulonglong2*>(&Wd[buf][nl][e][1][j]);
                ull a = acc0[e];
                FFMA2(a, wA.x, xa0.x, a); FFMA2(a, wA.y, xa0.y, a);
                FFMA2(a, wB.x, xa1.x, a); FFMA2(a, wB.y, xa1.y, a);
                acc0[e] = a;
                ull b = acc1[e];
                FFMA2(b, wA.x, xb0.x, b); FFMA2(b, wA.y, xb0.y, b);
                FFMA2(b, wB.x, xb1.x, b); FFMA2(b, wB.y, xb1.y, b);
                acc1[e] = b;
            }
        }
    };

    issue(0);
    issue(1);
#define P1_STAGE(s, WN) do { cp_wait<WN>(); __syncthreads(); compute(s); \
                             __syncthreads(); if ((s) + 2 < P1_STG) issue((s) + 2); } while (0)
    P1_STAGE(0, 1);
    P1_STAGE(1, 1);
    P1_STAGE(2, 1);
    P1_STAGE(3, 0);

    float* dst = g_s1 + (blockIdx.x & (SLOTS - 1)) * (B_ * 32);
#pragma unroll
    for (int e = 0; e < 16; ++e) {
        float lo, hi;
        UNPACK2(lo, hi, acc0[e]);
        atomicAdd(dst + (j * 16 + e) * B_ + gbb + lb0, lo + hi);
        UNPACK2(lo, hi, acc1[e]);
        atomicAdd(dst + (j * 16 + e) * B_ + gbb + lb1, lo + hi);
    }
}

// ======================= v1 = squash(0.5 * sum_slots s1) =======================
__global__ void v1_kernel() {
    const int b = threadIdx.x;
    float s[32];
#pragma unroll
    for (int k = 0; k < 32; ++k) s[k] = 0.0f;
#pragma unroll
    for (int sl = 0; sl < SLOTS; ++sl)
#pragma unroll
        for (int k = 0; k < 32; ++k)
            s[k] += g_s1[sl * (B_ * 32) + k * B_ + b];
#pragma unroll
    for (int k = 0; k < 32; ++k) s[k] *= 0.5f;
    float v[32];
    squash16(s, v);
    squash16(s + 16, v + 16);
#pragma unroll
    for (int k = 0; k < 32; ++k) g_v1[b * 32 + k] = v[k];   // [b][k] layout
}

// ======================= Pass 2 =======================
// 256 threads: j = tid&1, bl = tid>>1 (128 b per block). 16 n per block
// (4 stages x 4 n), cp.async double-buffered.
#define P2_NCH 4
#define P2_STG 4
#define P2_THR 256
#define P2_BG  128

__global__ __launch_bounds__(P2_THR, 2) void pass2_kernel(const float4* __restrict__ X,
                                                          const float4* __restrict__ Wg) {
    __shared__ float4 Wd[2][P2_NCH][16][2][2];
    __shared__ float4 xs[2][P2_BG][P2_NCH * 2 + 1];

    const int tid   = threadIdx.x;
    const int j     = tid & 1;
    const int bl    = tid >> 1;              // 0..127
    const int gbb   = blockIdx.y * P2_BG;
    const int b     = gbb + bl;
    const int nbase = blockIdx.x * (P2_NCH * P2_STG);

    // v1 for (b, j), packed into e-pairs (8 ull)
    ull v1p[8];
    {
        const float4* vp = reinterpret_cast<const float4*>(g_v1 + b * 32 + j * 16);
#pragma unroll
        for (int q = 0; q < 4; ++q) {
            float4 v = vp[q];
            PACK2(v1p[2 * q],     v.x, v.y);
            PACK2(v1p[2 * q + 1], v.z, v.w);
        }
    }

    ull accp[8];
    ull zero; PACK2(zero, 0.0f, 0.0f);
#pragma unroll
    for (int q = 0; q < 8; ++q) accp[q] = zero;

    auto issue = [&](int s) {
        const int buf = s & 1;
        const int n0  = nbase + s * P2_NCH;
        {   // W: 256 float4, 1 per thread
            int f  = tid;
            int jj = f & 1, h = (f >> 1) & 1, e = (f >> 2) & 15, nl = (f >> 6) & 3;
            cp16(&Wd[buf][nl][e][h][jj],
                 Wg + ((size_t)(jj * NIN_ + n0 + nl) * 16 + e) * 2 + h);
        }
#pragma unroll
        for (int it = 0; it < 4; ++it) {     // x: 1024 float4, 4 per thread
            int f = it * P2_THR + tid;
            int b2 = f >> 3, q = f & 7, nl = q >> 1, h = q & 1;
            cp16(&xs[buf][b2][nl * 2 + h],
                 X + ((size_t)(gbb + b2) * NIN_ + n0 + nl) * 2 + h);
        }
        CP_COMMIT();
    };

    auto compute = [&](int s) {
        const int buf = s & 1;
#pragma unroll
        for (int nl = 0; nl < P2_NCH; ++nl) {
            ulonglong2 x0 = *reinterpret_cast<const ulonglong2*>(&xs[buf][bl][nl * 2]);
            ulonglong2 x1 = *reinterpret_cast<const ulonglong2*>(&xs[buf][bl][nl * 2 + 1]);

            float u[16];
#pragma unroll
            for (int e = 0; e < 16; ++e) {
                ulonglong2 wA = *reinterpret_cast<const ulonglong2*>(&Wd[buf][nl][e][0][j]);
                ulonglong2 wB = *reinterpret_cast<const ulonglong2*>(&Wd[buf][nl][e][1][j]);
                ull t;
                FMUL2(t, wA.x, x0.x);
                FFMA2(t, wA.y, x0.y, t);
                FFMA2(t, wB.x, x1.x, t);
                FFMA2(t, wB.y, x1.y, t);
                float lo, hi;
                UNPACK2(lo, hi, t);
                u[e] = lo + hi;
            }

            ull up[8];
            ull t2 = zero;
#pragma unroll
            for (int q = 0; q < 8; ++q) {
                PACK2(up[q], u[2 * q], u[2 * q + 1]);
                FFMA2(t2, v1p[q], up[q], t2);
            }
            float tlo, thi;
            UNPACK2(tlo, thi, t2);
            float tj = tlo + thi;
            float to = __shfl_xor_sync(0xffffffffu, tj, 1);
            float c  = __fdividef(1.0f, 1.0f + __expf(to - tj));
            ull cd; PACK2(cd, c, c);
#pragma unroll
            for (int q = 0; q < 8; ++q)
                FFMA2(accp[q], cd, up[q], accp[q]);
        }
    };

    issue(0);
    issue(1);
#define P2_STAGE(s, WN) do { cp_wait<WN>(); __syncthreads(); compute(s); \
                             __syncthreads(); if ((s) + 2 < P2_STG) issue((s) + 2); } while (0)
    P2_STAGE(0, 1);
    P2_STAGE(1, 1);
    P2_STAGE(2, 1);
    P2_STAGE(3, 0);

    float* dst = g_s2 + (blockIdx.x & (SLOTS - 1)) * (B_ * 32);
#pragma unroll
    for (int q = 0; q < 8; ++q) {
        float lo, hi;
        UNPACK2(lo, hi, accp[q]);
        atomicAdd(dst + (j * 16 + 2 * q) * B_ + b,     lo);
        atomicAdd(dst + (j * 16 + 2 * q + 1) * B_ + b, hi);
    }
}

// ======================= Output =======================
__global__ void squash_out_kernel(float* __restrict__ out) {
    int t = blockIdx.x * blockDim.x + threadIdx.x;   // t = b*2 + j
    if (t < B_ * 2) {
        int b = t >> 1, j = t & 1;
        float s[16];
#pragma unroll
        for (int e = 0; e < 16; ++e) s[e] = 0.0f;
#pragma unroll
        for (int sl = 0; sl < SLOTS; ++sl)
#pragma unroll
            for (int e = 0; e < 16; ++e)
                s[e] += g_s2[sl * (B_ * 32) + (j * 16 + e) * B_ + b];
        float v[16];
        squash16(s, v);
#pragma unroll
        for (int e = 0; e < 16; ++e) out[t * 16 + e] = v[e];
    }
}

extern "C" void kernel_launch(void* const* d_in, const int* in_sizes, int n_in,
                              void* d_out, int out_size) {
    const float4* X = (const float4*)d_in[0];   // x: [256, 6912, 8] f32
    const float4* W = (const float4*)d_in[1];   // W: [2, 6912, 16, 8] f32
    float* out = (float*)d_out;                 // v: [256, 2, 16] f32

    zero_kernel<<<(SLOTS * B_ * 32 + 255) / 256, 256>>>();

    dim3 g1(NIN_ / (P1_NCH * P1_STG), B_ / P1_BG);   // 432 x 2
    pass1_kernel<<<g1, P1_THR>>>(X, W);

    v1_kernel<<<1, B_>>>();

    dim3 g2(NIN_ / (P2_NCH * P2_STG), B_ / P2_BG);   // 432 x 2
    pass2_kernel<<<g2, P2_THR>>>(X, W);

    squash_out_kernel<<<2, 256>>>(out);
}